// round 16
// baseline (speedup 1.0000x reference)
#include <cuda_runtime.h>
#include <cuda_fp16.h>
#include <cuda_pipeline.h>
#include <cstdint>
#include <math.h>

#define NN   50000
#define NE   200000
#define IND  512
#define HID  2000
#define LAT  128
#define MPAD 50048
#define K1A  1024
#define K1B  1024
#define K2A  4096
#define K2B  4096

__device__ __align__(128) int g_row[NE];
__device__ __align__(128) int g_col[NE];
__device__ __align__(128) float g_degE[NN];   // edge-degree accum; re-zeroed by k_disyinit
__device__ __align__(128) float g_deg[MPAD];
__device__ __align__(128) float g_dis[MPAD];
__device__ __align__(128) float g_Y[(size_t)NN * IND];
__device__ __align__(128) __half g_A3[(size_t)MPAD * K1A];
__device__ __align__(128) __half g_B3[(size_t)2048 * K1B];
__device__ __align__(128) __half g_H1s[(size_t)MPAD * K2A];
__device__ __align__(128) __half g_W2s[(size_t)LAT * K2B];
__device__ __align__(128) float g_H2[(size_t)MPAD * LAT];   // scatter SOURCE (immutable during scat2)
__device__ __align__(128) float g_O[(size_t)MPAD * LAT];    // scatter DEST

__device__ __forceinline__ uint32_t smem_u32(const void* p) {
    uint32_t a;
    asm("{ .reg .u64 t; cvta.to.shared.u64 t, %1; cvt.u32.u64 %0, t; }" : "=r"(a) : "l"(p));
    return a;
}
__device__ __forceinline__ uint32_t packh(__half a, __half b) {
    return (uint32_t)__half_as_ushort(a) | ((uint32_t)__half_as_ushort(b) << 16);
}
__device__ __forceinline__ void split2(float v, __half& h, __half& l) {
    h = __float2half_rn(v);
    l = __float2half_rn(v - __half2float(h));
}
__device__ __forceinline__ uint32_t swz(uint32_t o) { return o ^ ((o >> 3) & 0x30); }
__device__ __forceinline__ void red4(float* p, float a, float b, float c, float d) {
    asm volatile("red.global.add.v4.f32 [%0], {%1, %2, %3, %4};"
                 :: "l"(p), "f"(a), "f"(b), "f"(c), "f"(d) : "memory");
}

#define LDSM4(d, addr) \
    asm volatile("ldmatrix.sync.aligned.m8n8.x4.shared.b16 {%0,%1,%2,%3}, [%4];" \
        : "=r"((d)[0]), "=r"((d)[1]), "=r"((d)[2]), "=r"((d)[3]) : "r"(addr))

#define MMA(cc, a, b0, b1) \
    asm volatile("mma.sync.aligned.m16n8k16.row.col.f32.f16.f16.f32 " \
        "{%0,%1,%2,%3}, {%4,%5,%6,%7}, {%8,%9}, {%0,%1,%2,%3};" \
        : "+f"((cc)[0]), "+f"((cc)[1]), "+f"((cc)[2]), "+f"((cc)[3]) \
        : "r"((a)[0]), "r"((a)[1]), "r"((a)[2]), "r"((a)[3]), "r"(b0), "r"(b1))

// ---- launch 0: probe dtype + normalize indices + edge-degree accumulate ----
__global__ void k_normdeg(const void* __restrict__ ei) {
    const int* p32 = (const int*)ei;
    int s = 0;
#pragma unroll
    for (int i = 0; i < 64; i++) s |= p32[2 * i + 1];
    bool is32 = (s != 0);            // JAX x64-off => int32
    int e = blockIdx.x * blockDim.x + threadIdx.x;
    if (e < NE) {
        int r, c;
        if (is32) { r = p32[e]; c = p32[NE + e]; }
        else {
            const long long* p = (const long long*)ei;
            r = (int)p[e]; c = (int)p[NE + e];
        }
        g_row[e] = r; g_col[e] = c;
        atomicAdd(&g_degE[c], 1.0f);
    }
}
// ---- deg/dis finalize + self-loop Y init + degE reset ----
__global__ void k_disyinit(const float* __restrict__ x) {
    int idx = blockIdx.x * blockDim.x + threadIdx.x;
    bool main_ = idx < NN * 128;
    int i = 0; float dE = 0.0f;
    if (main_) { i = idx >> 7; dE = g_degE[i]; }
    __syncthreads();
    if (main_) {
        float deg = 1.0f + dE;
        if ((idx & 127) == 0) {
            g_degE[i] = 0.0f;        // restore for next replay (determinism)
            g_deg[i] = deg;
            g_dis[i] = rsqrtf(deg);
        }
        float sI = 1.0f / deg;
        float4 v = ((const float4*)x)[idx];
        ((float4*)g_Y)[idx] = make_float4(v.x * sI, v.y * sI, v.z * sI, v.w * sI);
    } else if (idx < NN * 128 + (MPAD - NN)) {
        int p = NN + (idx - NN * 128);
        g_deg[p] = 1.0f; g_dis[p] = 1.0f;
    }
}
// ---- edge scatter, layer 1 (reads x, writes Y) ----
__global__ void k_scat1(const float* __restrict__ x) {
    int gt = blockIdx.x * blockDim.x + threadIdx.x;
    int gw = gt >> 5, lane = gt & 31;
    if (gw >= NE) return;
    int r = g_row[gw], c = g_col[gw];
    float w = g_dis[r] * g_dis[c];
    const float4* xr = ((const float4*)x) + (size_t)r * 128;
    float* yr = g_Y + (size_t)c * IND;
#pragma unroll
    for (int t = 0; t < 4; t++) {
        int j = lane + t * 32;
        float4 v = xr[j];
        red4(yr + j * 4, w * v.x, w * v.y, w * v.z, w * v.w);
    }
}
// ---- split Y -> [hi|lo] fp16, 8 elems/thread ----
__global__ void k_splitA() {
    int idx = blockIdx.x * blockDim.x + threadIdx.x;
    if (idx < NN * IND / 8) {
        int i = idx >> 6, g = idx & 63;
        const float4* src = (const float4*)(g_Y + (size_t)i * IND + g * 8);
        float4 v0 = src[0], v1 = src[1];
        __half h0,l0,h1,l1,h2,l2,h3,l3,h4,l4,h5,l5,h6,l6,h7,l7;
        split2(v0.x,h0,l0); split2(v0.y,h1,l1); split2(v0.z,h2,l2); split2(v0.w,h3,l3);
        split2(v1.x,h4,l4); split2(v1.y,h5,l5); split2(v1.z,h6,l6); split2(v1.w,h7,l7);
        uint4 hv = make_uint4(packh(h0,h1), packh(h2,h3), packh(h4,h5), packh(h6,h7));
        uint4 lv = make_uint4(packh(l0,l1), packh(l2,l3), packh(l4,l5), packh(l6,l7));
        size_t ro = (size_t)i * K1A + g * 8;
        *(uint4*)(g_A3 + ro) = hv;
        *(uint4*)(g_A3 + ro + 512) = lv;
    }
}
// ---- W1 -> B3 [hi(512)|lo(512)] via smem transpose ----
__global__ void k_B3(const float* __restrict__ W1) {
    __shared__ float t[64][65];
    int bk = blockIdx.x, bn = blockIdx.y;
    int tid = threadIdx.x;
#pragma unroll
    for (int i = 0; i < 16; i++) {
        int e = tid + 256 * i, row = e >> 6, col = e & 63;
        int gn = bn * 64 + col;
        t[row][col] = (gn < HID) ? W1[(size_t)(bk * 64 + row) * HID + gn] : 0.0f;
    }
    __syncthreads();
#pragma unroll
    for (int i = 0; i < 16; i++) {
        int e = tid + 256 * i, nr = e >> 6, kc = e & 63;
        int gn = bn * 64 + nr;
        if (gn < HID) {
            __half h, l; split2(t[kc][nr], h, l);
            size_t ro = (size_t)gn * K1B + bk * 64 + kc;
            g_B3[ro] = h; g_B3[ro + 512] = l;
        }
    }
}
// ---- W2 -> W2s [hi(2048)|lo(2048)] ----
__global__ void k_W2s(const float* __restrict__ W2) {
    int idx = blockIdx.x * blockDim.x + threadIdx.x;
    if (idx < HID * LAT) {
        int n = idx & 127, k = idx >> 7;
        __half h, l; split2(W2[(size_t)k * LAT + n], h, l);
        size_t ro = (size_t)n * K2B;
        g_W2s[ro + k] = h; g_W2s[ro + 2048 + k] = l;
    }
}
// ---- edge scatter, layer 2 (reads immutable H2, writes O) ----
__global__ void k_scat2() {
    int gt = blockIdx.x * blockDim.x + threadIdx.x;
    int gw = gt >> 5, lane = gt & 31;
    if (gw >= NE) return;
    int r = g_row[gw], c = g_col[gw];
    float w = g_dis[r] * g_dis[c];
    float4 v = ((const float4*)g_H2)[(size_t)r * 32 + lane];
    red4(g_O + (size_t)c * LAT + lane * 4, w * v.x, w * v.y, w * v.z, w * v.w);
}
__global__ void k_final(float* __restrict__ out, const float* __restrict__ b2) {
    int idx = blockIdx.x * blockDim.x + threadIdx.x;
    if (idx < NN * 32) {
        float4 t = ((const float4*)g_O)[idx];
        float4 b = ((const float4*)b2)[idx & 31];
        float4 o;
        o.x = 1.0f / (1.0f + __expf(-(t.x + b.x)));
        o.y = 1.0f / (1.0f + __expf(-(t.y + b.y)));
        o.z = 1.0f / (1.0f + __expf(-(t.z + b.z)));
        o.w = 1.0f / (1.0f + __expf(-(t.w + b.w)));
        ((float4*)out)[idx] = o;
    }
}

// ---- shared warp-tile compute: C += A[32-k chunk] x B, from smem ----
__device__ __forceinline__ void gemm_pass(uint32_t As, uint32_t Bs, int m0, int n0,
                                          int lane, float c[2][8][4], int NT) {
    const int ra = m0 + (lane & 7) + 8 * ((lane >> 3) & 1);
    const int ca = 16 * (lane >> 4);
    const int rb = (lane & 7) + 8 * (lane >> 4);
    const int cb = 16 * ((lane >> 3) & 1);
#pragma unroll
    for (int ks = 0; ks < 2; ks++) {
        uint32_t a[2][4], b[4][4];
#pragma unroll
        for (int mf = 0; mf < 2; mf++)
            LDSM4(a[mf], As + swz((uint32_t)((ra + mf * 16) * 64 + ks * 32 + ca)));
#pragma unroll
        for (int nt = 0; nt < 4; nt++)
            if (nt < NT)
                LDSM4(b[nt], Bs + swz((uint32_t)((n0 + nt * 16 + rb) * 64 + ks * 32 + cb)));
#pragma unroll
        for (int mf = 0; mf < 2; mf++)
#pragma unroll
            for (int nt = 0; nt < 4; nt++)
                if (nt < NT) {
                    MMA(c[mf][2 * nt],     a[mf], b[nt][0], b[nt][1]);
                    MMA(c[mf][2 * nt + 1], a[mf], b[nt][2], b[nt][3]);
                }
    }
}

// ---------------- GEMM1: 128x128 tile, 256 thr, stage=[Ahi|Alo|Bhi|Blo] 32KB x3 ----
#define STG1   32768
#define G_SMEM (3 * STG1)

__device__ __forceinline__ void issue_stage1(int j, int stage, char* smem, int tid,
                                             int tmb, int tn) {
    char* buf = smem + stage * STG1;
#pragma unroll
    for (int q = 0; q < 2; q++) {
        int i = tid + 256 * q, row = i >> 2, seg = i & 3;   // 128 rows x 4 segs
        uint32_t sw = swz((uint32_t)(row * 64 + seg * 16));
        const __half* gaH = g_A3 + (size_t)(tmb * 128 + row) * K1A + j * 32 + seg * 8;
        const __half* gbH = g_B3 + (size_t)(tn * 128 + row) * K1B + j * 32 + seg * 8;
        __pipeline_memcpy_async(buf + sw,         gaH,       16);   // Ahi
        __pipeline_memcpy_async(buf + 8192 + sw,  gaH + 512, 16);   // Alo
        __pipeline_memcpy_async(buf + 16384 + sw, gbH,       16);   // Bhi
        __pipeline_memcpy_async(buf + 24576 + sw, gbH + 512, 16);   // Blo
    }
    __pipeline_commit();
}

__global__ void __launch_bounds__(256) k_gemm1(const float* __restrict__ bias) {
    extern __shared__ char smem[];
    const uint32_t sb = smem_u32(smem);
    const int tid = threadIdx.x, lane = tid & 31, w = tid >> 5;
    const int tn = blockIdx.x, tmb = blockIdx.y;
    const int m0 = (w & 3) * 32, n0 = (w >> 2) * 64;

    float c[2][8][4];
#pragma unroll
    for (int i = 0; i < 2; i++)
#pragma unroll
        for (int j = 0; j < 8; j++)
#pragma unroll
            for (int q = 0; q < 4; q++) c[i][j][q] = 0.0f;

    issue_stage1(0, 0, smem, tid, tmb, tn);
    issue_stage1(1, 1, smem, tid, tmb, tn);

#pragma unroll 1
    for (int j = 0; j < 16; j++) {
        if (j + 2 < 16) issue_stage1(j + 2, (j + 2) % 3, smem, tid, tmb, tn);
        else __pipeline_commit();
        __pipeline_wait_prior(2);
        __syncthreads();
        uint32_t bs = sb + (j % 3) * STG1;
        gemm_pass(bs,        bs + 16384, m0, n0, lane, c, 4);  // Ahi x Bhi
        gemm_pass(bs,        bs + 24576, m0, n0, lane, c, 4);  // Ahi x Blo
        gemm_pass(bs + 8192, bs + 16384, m0, n0, lane, c, 4);  // Alo x Bhi
        __syncthreads();   // protect buffer j%3 from prefetch of j+3
    }

    const int r0 = lane >> 2, c0 = (lane & 3) * 2;
#pragma unroll
    for (int mf = 0; mf < 2; mf++)
#pragma unroll
        for (int h = 0; h < 2; h++) {
            size_t m = (size_t)tmb * 128 + m0 + mf * 16 + r0 + 8 * h;
            __half* orow = g_H1s + m * K2A;
#pragma unroll
            for (int nf = 0; nf < 8; nf++) {
                int gn = tn * 128 + n0 + nf * 8 + c0;
                float v0 = (gn < HID)     ? fmaxf(c[mf][nf][2 * h]     + bias[gn],     0.0f) : 0.0f;
                float v1 = (gn + 1 < HID) ? fmaxf(c[mf][nf][2 * h + 1] + bias[gn + 1], 0.0f) : 0.0f;
                __half h0, l0, h1, l1;
                split2(v0, h0, l0); split2(v1, h1, l1);
                *(uint32_t*)(orow + gn)        = packh(h0, h1);
                *(uint32_t*)(orow + 2048 + gn) = packh(l0, l1);
            }
        }
}

// ---------------- GEMM2: 64x128 tile, 256 thr, stage=[Ahi|Alo|Bhi|Blo] 24KB x3 ----
#define STG2   24576
#define G2_SMEM (3 * STG2)

__device__ __forceinline__ void issue_stage2(int j, int stage, char* smem, int tid, int tmb) {
    char* buf = smem + stage * STG2;
    {   // A: 64 rows x 4 segs = 256 ops (hi + lo)
        int row = tid >> 2, seg = tid & 3;
        uint32_t sw = swz((uint32_t)(row * 64 + seg * 16));
        const __half* gaH = g_H1s + (size_t)(tmb * 64 + row) * K2A + j * 32 + seg * 8;
        __pipeline_memcpy_async(buf + sw,        gaH,        16);   // Ahi
        __pipeline_memcpy_async(buf + 4096 + sw, gaH + 2048, 16);   // Alo
    }
#pragma unroll
    for (int q = 0; q < 2; q++) {   // B: 128 rows x 4 segs = 512 ops (hi + lo)
        int i = tid + 256 * q, row = i >> 2, seg = i & 3;
        uint32_t sw = swz((uint32_t)(row * 64 + seg * 16));
        const __half* gbH = g_W2s + (size_t)row * K2B + j * 32 + seg * 8;
        __pipeline_memcpy_async(buf + 8192 + sw,  gbH,        16);  // Bhi
        __pipeline_memcpy_async(buf + 16384 + sw, gbH + 2048, 16);  // Blo
    }
    __pipeline_commit();
}

__device__ __forceinline__ void gemm_pass2(uint32_t As, uint32_t Bs, int m0, int n0,
                                           int lane, float c[2][4][4]) {
    const int ra = m0 + (lane & 7) + 8 * ((lane >> 3) & 1);
    const int ca = 16 * (lane >> 4);
    const int rb = (lane & 7) + 8 * (lane >> 4);
    const int cb = 16 * ((lane >> 3) & 1);
#pragma unroll
    for (int ks = 0; ks < 2; ks++) {
        uint32_t a[2][4], b[2][4];
#pragma unroll
        for (int mf = 0; mf < 2; mf++)
            LDSM4(a[mf], As + swz((uint32_t)((ra + mf * 16) * 64 + ks * 32 + ca)));
#pragma unroll
        for (int nt = 0; nt < 2; nt++)
            LDSM4(b[nt], Bs + swz((uint32_t)((n0 + nt * 16 + rb) * 64 + ks * 32 + cb)));
#pragma unroll
        for (int mf = 0; mf < 2; mf++)
#pragma unroll
            for (int nt = 0; nt < 2; nt++) {
                MMA(c[mf][2 * nt],     a[mf], b[nt][0], b[nt][1]);
                MMA(c[mf][2 * nt + 1], a[mf], b[nt][2], b[nt][3]);
            }
    }
}

__global__ void __launch_bounds__(256) k_gemm2() {
    extern __shared__ char smem[];
    const uint32_t sb = smem_u32(smem);
    const int tid = threadIdx.x, lane = tid & 31, w = tid >> 5;
    const int tmb = blockIdx.x;
    const int m0 = (w & 1) * 32, n0 = (w >> 1) * 32;

    float c[2][4][4];
#pragma unroll
    for (int i = 0; i < 2; i++)
#pragma unroll
        for (int j = 0; j < 4; j++)
#pragma unroll
            for (int q = 0; q < 4; q++) c[i][j][q] = 0.0f;

    issue_stage2(0, 0, smem, tid, tmb);
    issue_stage2(1, 1, smem, tid, tmb);

#pragma unroll 1
    for (int j = 0; j < 64; j++) {
        if (j + 2 < 64) issue_stage2(j + 2, (j + 2) % 3, smem, tid, tmb);
        else __pipeline_commit();
        __pipeline_wait_prior(2);
        __syncthreads();
        uint32_t bs = sb + (j % 3) * STG2;
        gemm_pass2(bs,        bs + 8192,  m0, n0, lane, c);  // Ahi x Bhi
        gemm_pass2(bs,        bs + 16384, m0, n0, lane, c);  // Ahi x Blo
        gemm_pass2(bs + 4096, bs + 8192,  m0, n0, lane, c);  // Alo x Bhi
        __syncthreads();
    }

    const int r0 = lane >> 2, c0 = (lane & 3) * 2;
#pragma unroll
    for (int mf = 0; mf < 2; mf++)
#pragma unroll
        for (int h = 0; h < 2; h++) {
            size_t m = (size_t)tmb * 64 + m0 + mf * 16 + r0 + 8 * h;
            float s = 1.0f / g_deg[m];
            float* hrow = g_H2 + m * LAT;
            float* orow = g_O + m * LAT;
#pragma unroll
            for (int nf = 0; nf < 4; nf++) {
                int gn = n0 + nf * 8 + c0;
                float v0 = c[mf][nf][2 * h], v1 = c[mf][nf][2 * h + 1];
                *(float2*)(hrow + gn) = make_float2(v0, v1);          // immutable scatter source
                *(float2*)(orow + gn) = make_float2(s * v0, s * v1);  // fused oinit (self-loop)
            }
        }
}

extern "C" void kernel_launch(void* const* d_in, const int* in_sizes, int n_in,
                              void* d_out, int out_size) {
    const float* x  = (const float*)d_in[0];
    const void*  ei = d_in[1];
    const float* W1 = (const float*)d_in[2];
    const float* b1 = (const float*)d_in[3];
    const float* W2 = (const float*)d_in[4];
    const float* b2 = (const float*)d_in[5];
    float* out = (float*)d_out;

    cudaFuncSetAttribute(k_gemm1, cudaFuncAttributeMaxDynamicSharedMemorySize, G_SMEM);
    cudaFuncSetAttribute(k_gemm2, cudaFuncAttributeMaxDynamicSharedMemorySize, G2_SMEM);

    k_normdeg<<<(NE + 255) / 256, 256>>>(ei);                    // 0
    k_disyinit<<<(NN * 128 + MPAD - NN + 255) / 256, 256>>>(x);  // 1
    k_scat1<<<(NE * 32 + 255) / 256, 256>>>(x);                  // 2
    k_splitA<<<(NN * IND / 8 + 255) / 256, 256>>>();             // 3  <- ncu slot
    k_B3<<<dim3(8, 32), 256>>>(W1);                              // 4
    k_W2s<<<(HID * LAT + 255) / 256, 256>>>(W2);                 // 5
    k_gemm1<<<dim3(16, MPAD / 128), 256, G_SMEM>>>(b1);          // 6
    k_gemm2<<<MPAD / 64, 256, G2_SMEM>>>();                      // 7
    k_scat2<<<(NE * 32 + 255) / 256, 256>>>();                   // 8
    k_final<<<(NN * 32 + 255) / 256, 256>>>(out, b2);            // 9
}

// round 17
// speedup vs baseline: 1.2937x; 1.2937x over previous
#include <cuda_runtime.h>
#include <cuda_fp16.h>
#include <cuda_pipeline.h>
#include <cstdint>
#include <math.h>

#define NN   50000
#define NE   200000
#define IND  512
#define HID  2000
#define LAT  128
#define MPAD 50048
#define K1A  1024
#define K1B  1536
#define K2A  2048
#define K2B  4096

__device__ __align__(128) int g_row[NE];
__device__ __align__(128) int g_col[NE];
__device__ __align__(128) float g_degE[NN];   // edge-degree accum; re-zeroed by k_disyinit
__device__ __align__(128) float g_deg[MPAD];
__device__ __align__(128) float g_dis[MPAD];
__device__ __align__(128) float g_Y[(size_t)NN * IND];
__device__ __align__(128) __half g_A3[(size_t)MPAD * K1A];
__device__ __align__(128) __half g_B3[(size_t)2048 * K1B];
__device__ __align__(128) __half g_H1s[(size_t)MPAD * K2A];   // hi only now
__device__ __align__(128) __half g_W2s[(size_t)LAT * K2B];
__device__ __align__(128) float g_H2[(size_t)MPAD * LAT];   // scatter SOURCE (immutable during scat2)
__device__ __align__(128) float g_O[(size_t)MPAD * LAT];    // scatter DEST

__device__ __forceinline__ uint32_t smem_u32(const void* p) {
    uint32_t a;
    asm("{ .reg .u64 t; cvta.to.shared.u64 t, %1; cvt.u32.u64 %0, t; }" : "=r"(a) : "l"(p));
    return a;
}
__device__ __forceinline__ uint32_t packh(__half a, __half b) {
    return (uint32_t)__half_as_ushort(a) | ((uint32_t)__half_as_ushort(b) << 16);
}
__device__ __forceinline__ void split2(float v, __half& h, __half& l) {
    h = __float2half_rn(v);
    l = __float2half_rn(v - __half2float(h));
}
__device__ __forceinline__ uint32_t swz(uint32_t o) { return o ^ ((o >> 3) & 0x30); }
__device__ __forceinline__ void red4(float* p, float a, float b, float c, float d) {
    asm volatile("red.global.add.v4.f32 [%0], {%1, %2, %3, %4};"
                 :: "l"(p), "f"(a), "f"(b), "f"(c), "f"(d) : "memory");
}

#define LDSM4(d, addr) \
    asm volatile("ldmatrix.sync.aligned.m8n8.x4.shared.b16 {%0,%1,%2,%3}, [%4];" \
        : "=r"((d)[0]), "=r"((d)[1]), "=r"((d)[2]), "=r"((d)[3]) : "r"(addr))

#define MMA(cc, a, b0, b1) \
    asm volatile("mma.sync.aligned.m16n8k16.row.col.f32.f16.f16.f32 " \
        "{%0,%1,%2,%3}, {%4,%5,%6,%7}, {%8,%9}, {%0,%1,%2,%3};" \
        : "+f"((cc)[0]), "+f"((cc)[1]), "+f"((cc)[2]), "+f"((cc)[3]) \
        : "r"((a)[0]), "r"((a)[1]), "r"((a)[2]), "r"((a)[3]), "r"(b0), "r"(b1))

// ---- launch 0: probe dtype + normalize indices + edge-degree accumulate ----
__global__ void k_normdeg(const void* __restrict__ ei) {
    const int* p32 = (const int*)ei;
    int s = 0;
#pragma unroll
    for (int i = 0; i < 64; i++) s |= p32[2 * i + 1];
    bool is32 = (s != 0);            // JAX x64-off => int32
    int e = blockIdx.x * blockDim.x + threadIdx.x;
    if (e < NE) {
        int r, c;
        if (is32) { r = p32[e]; c = p32[NE + e]; }
        else {
            const long long* p = (const long long*)ei;
            r = (int)p[e]; c = (int)p[NE + e];
        }
        g_row[e] = r; g_col[e] = c;
        atomicAdd(&g_degE[c], 1.0f);
    }
}
// ---- deg/dis finalize + self-loop Y init + degE reset ----
__global__ void k_disyinit(const float* __restrict__ x) {
    int idx = blockIdx.x * blockDim.x + threadIdx.x;
    bool main_ = idx < NN * 128;
    int i = 0; float dE = 0.0f;
    if (main_) { i = idx >> 7; dE = g_degE[i]; }
    __syncthreads();
    if (main_) {
        float deg = 1.0f + dE;
        if ((idx & 127) == 0) {
            g_degE[i] = 0.0f;        // restore for next replay (determinism)
            g_deg[i] = deg;
            g_dis[i] = rsqrtf(deg);
        }
        float sI = 1.0f / deg;
        float4 v = ((const float4*)x)[idx];
        ((float4*)g_Y)[idx] = make_float4(v.x * sI, v.y * sI, v.z * sI, v.w * sI);
    } else if (idx < NN * 128 + (MPAD - NN)) {
        int p = NN + (idx - NN * 128);
        g_deg[p] = 1.0f; g_dis[p] = 1.0f;
    }
}
// ---- edge scatter, layer 1 (reads x, writes Y) ----
__global__ void k_scat1(const float* __restrict__ x) {
    int gt = blockIdx.x * blockDim.x + threadIdx.x;
    int gw = gt >> 5, lane = gt & 31;
    if (gw >= NE) return;
    int r = g_row[gw], c = g_col[gw];
    float w = g_dis[r] * g_dis[c];
    const float4* xr = ((const float4*)x) + (size_t)r * 128;
    float* yr = g_Y + (size_t)c * IND;
#pragma unroll
    for (int t = 0; t < 4; t++) {
        int j = lane + t * 32;
        float4 v = xr[j];
        red4(yr + j * 4, w * v.x, w * v.y, w * v.z, w * v.w);
    }
}
// ---- split Y -> [hi|lo] fp16, 8 elems/thread ----
__global__ void k_splitA() {
    int idx = blockIdx.x * blockDim.x + threadIdx.x;
    if (idx < NN * IND / 8) {
        int i = idx >> 6, g = idx & 63;
        const float4* src = (const float4*)(g_Y + (size_t)i * IND + g * 8);
        float4 v0 = src[0], v1 = src[1];
        __half h0,l0,h1,l1,h2,l2,h3,l3,h4,l4,h5,l5,h6,l6,h7,l7;
        split2(v0.x,h0,l0); split2(v0.y,h1,l1); split2(v0.z,h2,l2); split2(v0.w,h3,l3);
        split2(v1.x,h4,l4); split2(v1.y,h5,l5); split2(v1.z,h6,l6); split2(v1.w,h7,l7);
        uint4 hv = make_uint4(packh(h0,h1), packh(h2,h3), packh(h4,h5), packh(h6,h7));
        uint4 lv = make_uint4(packh(l0,l1), packh(l2,l3), packh(l4,l5), packh(l6,l7));
        size_t ro = (size_t)i * K1A + g * 8;
        *(uint4*)(g_A3 + ro) = hv;
        *(uint4*)(g_A3 + ro + 512) = lv;
    }
}
// ---- W1 -> B3 [hi(512)|lo(512)|hi(512)] via smem transpose ----
__global__ void k_B3(const float* __restrict__ W1) {
    __shared__ float t[64][65];
    int bk = blockIdx.x, bn = blockIdx.y;
    int tid = threadIdx.x;
#pragma unroll
    for (int i = 0; i < 16; i++) {
        int e = tid + 256 * i, row = e >> 6, col = e & 63;
        int gn = bn * 64 + col;
        t[row][col] = (gn < HID) ? W1[(size_t)(bk * 64 + row) * HID + gn] : 0.0f;
    }
    __syncthreads();
#pragma unroll
    for (int i = 0; i < 16; i++) {
        int e = tid + 256 * i, nr = e >> 6, kc = e & 63;
        int gn = bn * 64 + nr;
        if (gn < HID) {
            __half h, l; split2(t[kc][nr], h, l);
            size_t ro = (size_t)gn * K1B + bk * 64 + kc;
            g_B3[ro] = h; g_B3[ro + 512] = l; g_B3[ro + 1024] = h;
        }
    }
}
// ---- W2 -> W2s [hi(2048)|lo(2048)] ----
__global__ void k_W2s(const float* __restrict__ W2) {
    int idx = blockIdx.x * blockDim.x + threadIdx.x;
    if (idx < HID * LAT) {
        int n = idx & 127, k = idx >> 7;
        __half h, l; split2(W2[(size_t)k * LAT + n], h, l);
        size_t ro = (size_t)n * K2B;
        g_W2s[ro + k] = h; g_W2s[ro + 2048 + k] = l;
    }
}
// ---- edge scatter, layer 2 (reads immutable H2, writes O) ----
__global__ void k_scat2() {
    int gt = blockIdx.x * blockDim.x + threadIdx.x;
    int gw = gt >> 5, lane = gt & 31;
    if (gw >= NE) return;
    int r = g_row[gw], c = g_col[gw];
    float w = g_dis[r] * g_dis[c];
    float4 v = ((const float4*)g_H2)[(size_t)r * 32 + lane];
    red4(g_O + (size_t)c * LAT + lane * 4, w * v.x, w * v.y, w * v.z, w * v.w);
}
__global__ void k_final(float* __restrict__ out, const float* __restrict__ b2) {
    int idx = blockIdx.x * blockDim.x + threadIdx.x;
    if (idx < NN * 32) {
        float4 t = ((const float4*)g_O)[idx];
        float4 b = ((const float4*)b2)[idx & 31];
        float4 o;
        o.x = 1.0f / (1.0f + __expf(-(t.x + b.x)));
        o.y = 1.0f / (1.0f + __expf(-(t.y + b.y)));
        o.z = 1.0f / (1.0f + __expf(-(t.z + b.z)));
        o.w = 1.0f / (1.0f + __expf(-(t.w + b.w)));
        ((float4*)out)[idx] = o;
    }
}

// ---------------- GEMM1: 128x128 tile, m16n8k16 fp16, 4-stage cp.async (round-14) ----
#define STG1   16384
#define G_SMEM (4 * STG1)

__device__ __forceinline__ void issue_stage1(int kc, int stage, char* smem, int tid,
                                             int tmb, int tn) {
    int aOff = (kc % 16) * 32 + (kc >= 32 ? 512 : 0);
    int bOff = kc * 32;
    char* bufA = smem + stage * STG1;
    char* bufB = bufA + 8192;
#pragma unroll
    for (int j = 0; j < 2; j++) {
        int i = tid + 256 * j, row = i >> 2, seg = i & 3;
        uint32_t sw = swz((uint32_t)(row * 64 + seg * 16));
        const __half* ga = g_A3 + (size_t)(tmb * 128 + row) * K1A + aOff + seg * 8;
        const __half* gb = g_B3 + (size_t)(tn * 128 + row) * K1B + bOff + seg * 8;
        __pipeline_memcpy_async(bufA + sw, ga, 16);
        __pipeline_memcpy_async(bufB + sw, gb, 16);
    }
    __pipeline_commit();
}

__device__ __forceinline__ void gemm_stage1(uint32_t As, uint32_t Bs, int m0, int n0,
                                            int lane, float c[2][8][4]) {
    const int ra = m0 + (lane & 7) + 8 * ((lane >> 3) & 1);
    const int ca = 16 * (lane >> 4);
    const int rb = (lane & 7) + 8 * (lane >> 4);
    const int cb = 16 * ((lane >> 3) & 1);
#pragma unroll
    for (int ks = 0; ks < 2; ks++) {
        uint32_t a[2][4], b[4][4];
#pragma unroll
        for (int mf = 0; mf < 2; mf++)
            LDSM4(a[mf], As + swz((uint32_t)((ra + mf * 16) * 64 + ks * 32 + ca)));
#pragma unroll
        for (int nt = 0; nt < 4; nt++)
            LDSM4(b[nt], Bs + swz((uint32_t)((n0 + nt * 16 + rb) * 64 + ks * 32 + cb)));
#pragma unroll
        for (int mf = 0; mf < 2; mf++)
#pragma unroll
            for (int nt = 0; nt < 4; nt++) {
                MMA(c[mf][2 * nt],     a[mf], b[nt][0], b[nt][1]);
                MMA(c[mf][2 * nt + 1], a[mf], b[nt][2], b[nt][3]);
            }
    }
}

__global__ void __launch_bounds__(256) k_gemm1(const float* __restrict__ bias) {
    extern __shared__ char smem[];
    const uint32_t sb = smem_u32(smem);
    const int tid = threadIdx.x, lane = tid & 31, w = tid >> 5;
    const int tn = blockIdx.x, tmb = blockIdx.y;
    const int m0 = (w & 3) * 32, n0 = (w >> 2) * 64;

    float c[2][8][4];
#pragma unroll
    for (int i = 0; i < 2; i++)
#pragma unroll
        for (int j = 0; j < 8; j++)
#pragma unroll
            for (int q = 0; q < 4; q++) c[i][j][q] = 0.0f;

    issue_stage1(0, 0, smem, tid, tmb, tn);
    issue_stage1(1, 1, smem, tid, tmb, tn);

#pragma unroll 1
    for (int kc = 0; kc < 48; kc++) {
        if (kc + 2 < 48) issue_stage1(kc + 2, (kc + 2) & 3, smem, tid, tmb, tn);
        else __pipeline_commit();
        __pipeline_wait_prior(2);
        __syncthreads();
        uint32_t As = sb + (kc & 3) * STG1;
        gemm_stage1(As, As + 8192, m0, n0, lane, c);
    }

    const int r0 = lane >> 2, c0 = (lane & 3) * 2;
#pragma unroll
    for (int mf = 0; mf < 2; mf++)
#pragma unroll
        for (int h = 0; h < 2; h++) {
            size_t m = (size_t)tmb * 128 + m0 + mf * 16 + r0 + 8 * h;
            __half* orow = g_H1s + m * K2A;
#pragma unroll
            for (int nf = 0; nf < 8; nf++) {
                int gn = tn * 128 + n0 + nf * 8 + c0;
                float v0 = (gn < HID)     ? fmaxf(c[mf][nf][2 * h]     + bias[gn],     0.0f) : 0.0f;
                float v1 = (gn + 1 < HID) ? fmaxf(c[mf][nf][2 * h + 1] + bias[gn + 1], 0.0f) : 0.0f;
                // store hi only (layer-2 drops the A-lo correction term)
                *(uint32_t*)(orow + gn) = packh(__float2half_rn(v0), __float2half_rn(v1));
            }
        }
}

// ---------------- GEMM2: 64x128 tile, K=4096 plain (A=H1hi, B=[W2hi|W2lo]) ----
#define STG2   12288
#define G2_SMEM (4 * STG2)

__device__ __forceinline__ void issue_stage2(int kc, int stage, char* smem, int tid, int tmb) {
    int aOff = (kc & 63) * 32;          // A (2048 wide) reused for both B halves
    int bOff = kc * 32;                 // B spans full 4096
    char* bufA = smem + stage * STG2;
    char* bufB = bufA + 4096;
    {
        int row = tid >> 2, seg = tid & 3;
        uint32_t sw = swz((uint32_t)(row * 64 + seg * 16));
        const __half* ga = g_H1s + (size_t)(tmb * 64 + row) * K2A + aOff + seg * 8;
        __pipeline_memcpy_async(bufA + sw, ga, 16);
    }
#pragma unroll
    for (int j = 0; j < 2; j++) {
        int i = tid + 256 * j, row = i >> 2, seg = i & 3;
        uint32_t sw = swz((uint32_t)(row * 64 + seg * 16));
        const __half* gb = g_W2s + (size_t)row * K2B + bOff + seg * 8;
        __pipeline_memcpy_async(bufB + sw, gb, 16);
    }
    __pipeline_commit();
}

__device__ __forceinline__ void gemm_stage2(uint32_t As, uint32_t Bs, int m0, int n0,
                                            int lane, float c[2][4][4]) {
    const int ra = m0 + (lane & 7) + 8 * ((lane >> 3) & 1);
    const int ca = 16 * (lane >> 4);
    const int rb = (lane & 7) + 8 * (lane >> 4);
    const int cb = 16 * ((lane >> 3) & 1);
#pragma unroll
    for (int ks = 0; ks < 2; ks++) {
        uint32_t a[2][4], b[2][4];
#pragma unroll
        for (int mf = 0; mf < 2; mf++)
            LDSM4(a[mf], As + swz((uint32_t)((ra + mf * 16) * 64 + ks * 32 + ca)));
#pragma unroll
        for (int nt = 0; nt < 2; nt++)
            LDSM4(b[nt], Bs + swz((uint32_t)((n0 + nt * 16 + rb) * 64 + ks * 32 + cb)));
#pragma unroll
        for (int mf = 0; mf < 2; mf++)
#pragma unroll
            for (int nt = 0; nt < 2; nt++) {
                MMA(c[mf][2 * nt],     a[mf], b[nt][0], b[nt][1]);
                MMA(c[mf][2 * nt + 1], a[mf], b[nt][2], b[nt][3]);
            }
    }
}

__global__ void __launch_bounds__(256) k_gemm2() {
    extern __shared__ char smem[];
    const uint32_t sb = smem_u32(smem);
    const int tid = threadIdx.x, lane = tid & 31, w = tid >> 5;
    const int tmb = blockIdx.x;
    const int m0 = (w & 1) * 32, n0 = (w >> 1) * 32;

    float c[2][4][4];
#pragma unroll
    for (int i = 0; i < 2; i++)
#pragma unroll
        for (int j = 0; j < 4; j++)
#pragma unroll
            for (int q = 0; q < 4; q++) c[i][j][q] = 0.0f;

    issue_stage2(0, 0, smem, tid, tmb);
    issue_stage2(1, 1, smem, tid, tmb);

#pragma unroll 1
    for (int kc = 0; kc < 128; kc++) {
        if (kc + 2 < 128) issue_stage2(kc + 2, (kc + 2) & 3, smem, tid, tmb);
        else __pipeline_commit();
        __pipeline_wait_prior(2);
        __syncthreads();
        uint32_t As = sb + (kc & 3) * STG2;
        gemm_stage2(As, As + 4096, m0, n0, lane, c);
    }

    const int r0 = lane >> 2, c0 = (lane & 3) * 2;
#pragma unroll
    for (int mf = 0; mf < 2; mf++)
#pragma unroll
        for (int h = 0; h < 2; h++) {
            size_t m = (size_t)tmb * 64 + m0 + mf * 16 + r0 + 8 * h;
            float s = 1.0f / g_deg[m];
            float* hrow = g_H2 + m * LAT;
            float* orow = g_O + m * LAT;
#pragma unroll
            for (int nf = 0; nf < 4; nf++) {
                int gn = n0 + nf * 8 + c0;
                float v0 = c[mf][nf][2 * h], v1 = c[mf][nf][2 * h + 1];
                *(float2*)(hrow + gn) = make_float2(v0, v1);          // immutable scatter source
                *(float2*)(orow + gn) = make_float2(s * v0, s * v1);  // fused oinit (self-loop)
            }
        }
}

extern "C" void kernel_launch(void* const* d_in, const int* in_sizes, int n_in,
                              void* d_out, int out_size) {
    const float* x  = (const float*)d_in[0];
    const void*  ei = d_in[1];
    const float* W1 = (const float*)d_in[2];
    const float* b1 = (const float*)d_in[3];
    const float* W2 = (const float*)d_in[4];
    const float* b2 = (const float*)d_in[5];
    float* out = (float*)d_out;

    cudaFuncSetAttribute(k_gemm1, cudaFuncAttributeMaxDynamicSharedMemorySize, G_SMEM);
    cudaFuncSetAttribute(k_gemm2, cudaFuncAttributeMaxDynamicSharedMemorySize, G2_SMEM);

    k_normdeg<<<(NE + 255) / 256, 256>>>(ei);                    // 0
    k_disyinit<<<(NN * 128 + MPAD - NN + 255) / 256, 256>>>(x);  // 1
    k_scat1<<<(NE * 32 + 255) / 256, 256>>>(x);                  // 2
    k_splitA<<<(NN * IND / 8 + 255) / 256, 256>>>();             // 3  <- ncu slot
    k_B3<<<dim3(8, 32), 256>>>(W1);                              // 4
    k_W2s<<<(HID * LAT + 255) / 256, 256>>>(W2);                 // 5
    k_gemm1<<<dim3(16, MPAD / 128), 256, G_SMEM>>>(b1);          // 6
    k_gemm2<<<MPAD / 64, 256, G2_SMEM>>>();                      // 7
    k_scat2<<<(NE * 32 + 255) / 256, 256>>>();                   // 8
    k_final<<<(NN * 32 + 255) / 256, 256>>>(out, b2);            // 9
}